// round 1
// baseline (speedup 1.0000x reference)
#include <cuda_runtime.h>

// ---------------------------------------------------------------------------
// GroupAttention (Swin window attention), fp32 baseline
// B=32, N=4096 (64x64), C=128, WS=8 -> G=64 windows, S=64 tokens/window
// heads=4, hd=32. Pipeline: QKV GEMM (gathered) -> window attention -> proj.
// ---------------------------------------------------------------------------

#define B_    32
#define NTOK  4096
#define C_    128
#define G_    64
#define S_    64
#define NH    4
#define HD    32

// scratch (device globals; allocation-free)
__device__ float g_qkv[(size_t)B_ * G_ * S_ * 384];  // [B*G][S][384]  (~201MB)
__device__ float g_att[(size_t)B_ * NTOK * C_];      // [B][N][C]      (~64MB)

__device__ __forceinline__ int token_index(int g, int s) {
    // n = (g/8)*512 + (s/8)*64 + (g%8)*8 + (s%8)
    return ((g >> 3) << 9) + ((s >> 3) << 6) + ((g & 7) << 3) + (s & 7);
}

// ---------------------------------------------------------------------------
// QKV GEMM: out[b,g,s,o] = sum_c x[b, n(g,s), c] * w_qkv[o, c]
// Block computes 128 rows (2 windows) x 128 cols, K=128 single pass.
// grid = (3 col tiles, 1024 window-pairs), 256 threads.
// Shared rows padded to 132 floats (keeps float4 alignment, kills conflicts).
// ---------------------------------------------------------------------------
__global__ void __launch_bounds__(256) qkv_kernel(const float* __restrict__ x,
                                                  const float* __restrict__ w) {
    extern __shared__ float smem[];
    float* As = smem;              // [128][132]  As[r][k]
    float* Bs = smem + 128 * 132;  // [128][132]  Bs[o_local][k]

    const int tid = threadIdx.x;
    const int tx = tid & 15, ty = tid >> 4;
    const int o0 = blockIdx.x * 128;
    const int pair = blockIdx.y;
    const int b = pair >> 5;          // 32 pairs per batch
    const int g0 = (pair & 31) << 1;  // two consecutive windows

    // load A: gathered x rows (coalesced float4, conflict-free STS)
    #pragma unroll
    for (int it = 0; it < 16; it++) {
        int fidx = tid + it * 256;   // 0..4095 float4s
        int r = fidx >> 5;           // 0..127
        int c4 = fidx & 31;          // 0..31
        int g = g0 + (r >> 6);
        int s = r & 63;
        int n = token_index(g, s);
        float4 v = *(const float4*)(x + ((size_t)b * NTOK + n) * C_ + c4 * 4);
        *(float4*)(As + r * 132 + c4 * 4) = v;
    }
    // load B: w_qkv rows o0..o0+127
    #pragma unroll
    for (int it = 0; it < 16; it++) {
        int fidx = tid + it * 256;
        int r = fidx >> 5;
        int c4 = fidx & 31;
        float4 v = *(const float4*)(w + (size_t)(o0 + r) * C_ + c4 * 4);
        *(float4*)(Bs + r * 132 + c4 * 4) = v;
    }
    __syncthreads();

    float acc[8][8];
    #pragma unroll
    for (int i = 0; i < 8; i++)
        #pragma unroll
        for (int j = 0; j < 8; j++) acc[i][j] = 0.f;

    #pragma unroll 4
    for (int k0 = 0; k0 < 128; k0 += 4) {
        float4 a4[8], b4[8];
        #pragma unroll
        for (int i = 0; i < 8; i++)
            a4[i] = *(const float4*)(As + (ty + 16 * i) * 132 + k0);
        #pragma unroll
        for (int j = 0; j < 8; j++)
            b4[j] = *(const float4*)(Bs + (tx + 16 * j) * 132 + k0);
        #pragma unroll
        for (int i = 0; i < 8; i++)
            #pragma unroll
            for (int j = 0; j < 8; j++) {
                acc[i][j] += a4[i].x * b4[j].x;
                acc[i][j] += a4[i].y * b4[j].y;
                acc[i][j] += a4[i].z * b4[j].z;
                acc[i][j] += a4[i].w * b4[j].w;
            }
    }

    // epilogue: write to g_qkv[(b*64+g)*64 + s][o]
    #pragma unroll
    for (int i = 0; i < 8; i++) {
        int r = ty + 16 * i;
        int g = g0 + (r >> 6);
        int s = r & 63;
        size_t base = (((size_t)(b * G_ + g)) * S_ + s) * 384;
        #pragma unroll
        for (int j = 0; j < 8; j++)
            g_qkv[base + o0 + tx + 16 * j] = acc[i][j];
    }
}

// ---------------------------------------------------------------------------
// Window attention: one block per (b,g). 256 threads = 4 heads x 64 tokens.
// Whole window qkv (64x384) in shared; K/V reads are warp-broadcast.
// Writes directly to un-windowed [B,N,C] layout for the proj GEMM.
// ---------------------------------------------------------------------------
__global__ void __launch_bounds__(256) attn_kernel() {
    extern __shared__ float sh[];  // [64][388]
    const int tid = threadIdx.x;
    const int bg = blockIdx.x;     // b*64 + g

    const float* base = g_qkv + (size_t)bg * (S_ * 384);
    #pragma unroll
    for (int it = 0; it < 24; it++) {
        int fidx = tid + it * 256;   // 0..6143 float4s (64 rows x 96)
        int r = fidx / 96;
        int c4 = fidx % 96;
        *(float4*)(sh + r * 388 + c4 * 4) =
            *(const float4*)(base + r * 384 + c4 * 4);
    }
    __syncthreads();

    const int head = tid >> 6;
    const int s = tid & 63;
    const int hb = head * HD;
    const float scale = 0.1767766952966369f;  // 1/sqrt(32)

    float4 q4[8];
    #pragma unroll
    for (int d4 = 0; d4 < 8; d4++)
        q4[d4] = *(const float4*)(sh + s * 388 + hb + 4 * d4);

    // scores
    float att[64];
    float mx = -1e30f;
    #pragma unroll
    for (int t = 0; t < 64; t++) {
        const float* kr = sh + t * 388 + 128 + hb;
        float s0 = 0.f, s1 = 0.f, s2 = 0.f, s3 = 0.f;
        #pragma unroll
        for (int d4 = 0; d4 < 8; d4++) {
            float4 k4 = *(const float4*)(kr + 4 * d4);
            s0 += q4[d4].x * k4.x;
            s1 += q4[d4].y * k4.y;
            s2 += q4[d4].z * k4.z;
            s3 += q4[d4].w * k4.w;
        }
        float a = (s0 + s1) + (s2 + s3);
        att[t] = a;
        mx = fmaxf(mx, a);
    }

    // fused exp + sum + PV
    float sum = 0.f;
    float4 o4[8];
    #pragma unroll
    for (int d4 = 0; d4 < 8; d4++) o4[d4] = make_float4(0.f, 0.f, 0.f, 0.f);

    #pragma unroll
    for (int t = 0; t < 64; t++) {
        float e = __expf((att[t] - mx) * scale);
        sum += e;
        const float* vr = sh + t * 388 + 256 + hb;
        #pragma unroll
        for (int d4 = 0; d4 < 8; d4++) {
            float4 v4 = *(const float4*)(vr + 4 * d4);
            o4[d4].x += e * v4.x;
            o4[d4].y += e * v4.y;
            o4[d4].z += e * v4.z;
            o4[d4].w += e * v4.w;
        }
    }
    float inv = 1.f / sum;

    const int b = bg >> 6, g = bg & 63;
    const int n = token_index(g, s);
    float* orow = g_att + ((size_t)b * NTOK + n) * C_ + hb;
    #pragma unroll
    for (int d4 = 0; d4 < 8; d4++) {
        float4 v = o4[d4];
        v.x *= inv; v.y *= inv; v.z *= inv; v.w *= inv;
        *(float4*)(orow + 4 * d4) = v;
    }
}

// ---------------------------------------------------------------------------
// Output projection: out[row,o] = sum_c g_att[row,c] * w_proj[o,c] + b_proj[o]
// Same 128x128x128 tile template. grid = 1024 row blocks.
// ---------------------------------------------------------------------------
__global__ void __launch_bounds__(256) proj_kernel(const float* __restrict__ wp,
                                                   const float* __restrict__ bp,
                                                   float* __restrict__ out) {
    extern __shared__ float smem[];
    float* As = smem;              // [128][132]
    float* Bs = smem + 128 * 132;  // [128][132]

    const int tid = threadIdx.x;
    const int tx = tid & 15, ty = tid >> 4;
    const size_t row0 = (size_t)blockIdx.x * 128;

    #pragma unroll
    for (int it = 0; it < 16; it++) {
        int fidx = tid + it * 256;
        int r = fidx >> 5;
        int c4 = fidx & 31;
        float4 v = *(const float4*)(g_att + (row0 + r) * C_ + c4 * 4);
        *(float4*)(As + r * 132 + c4 * 4) = v;
    }
    #pragma unroll
    for (int it = 0; it < 16; it++) {
        int fidx = tid + it * 256;
        int r = fidx >> 5;
        int c4 = fidx & 31;
        float4 v = *(const float4*)(wp + (size_t)r * C_ + c4 * 4);
        *(float4*)(Bs + r * 132 + c4 * 4) = v;
    }
    __syncthreads();

    float acc[8][8];
    #pragma unroll
    for (int i = 0; i < 8; i++)
        #pragma unroll
        for (int j = 0; j < 8; j++) acc[i][j] = 0.f;

    #pragma unroll 4
    for (int k0 = 0; k0 < 128; k0 += 4) {
        float4 a4[8], b4[8];
        #pragma unroll
        for (int i = 0; i < 8; i++)
            a4[i] = *(const float4*)(As + (ty + 16 * i) * 132 + k0);
        #pragma unroll
        for (int j = 0; j < 8; j++)
            b4[j] = *(const float4*)(Bs + (tx + 16 * j) * 132 + k0);
        #pragma unroll
        for (int i = 0; i < 8; i++)
            #pragma unroll
            for (int j = 0; j < 8; j++) {
                acc[i][j] += a4[i].x * b4[j].x;
                acc[i][j] += a4[i].y * b4[j].y;
                acc[i][j] += a4[i].z * b4[j].z;
                acc[i][j] += a4[i].w * b4[j].w;
            }
    }

    #pragma unroll
    for (int i = 0; i < 8; i++) {
        size_t r = row0 + ty + 16 * i;
        #pragma unroll
        for (int j = 0; j < 8; j++) {
            int o = tx + 16 * j;
            out[r * C_ + o] = acc[i][j] + bp[o];
        }
    }
}

// ---------------------------------------------------------------------------
extern "C" void kernel_launch(void* const* d_in, const int* in_sizes, int n_in,
                              void* d_out, int out_size) {
    (void)in_sizes; (void)n_in; (void)out_size;
    const float* x      = (const float*)d_in[0];
    const float* w_qkv  = (const float*)d_in[1];
    const float* w_proj = (const float*)d_in[2];
    const float* b_proj = (const float*)d_in[3];
    float* out = (float*)d_out;

    const int SMEM_GEMM = 2 * 128 * 132 * 4;  // 135168 B
    const int SMEM_ATTN = 64 * 388 * 4;       //  99328 B
    cudaFuncSetAttribute(qkv_kernel,  cudaFuncAttributeMaxDynamicSharedMemorySize, SMEM_GEMM);
    cudaFuncSetAttribute(attn_kernel, cudaFuncAttributeMaxDynamicSharedMemorySize, SMEM_ATTN);
    cudaFuncSetAttribute(proj_kernel, cudaFuncAttributeMaxDynamicSharedMemorySize, SMEM_GEMM);

    qkv_kernel<<<dim3(3, 1024), 256, SMEM_GEMM>>>(x, w_qkv);
    attn_kernel<<<B_ * G_, 256, SMEM_ATTN>>>();
    proj_kernel<<<1024, 256, SMEM_GEMM>>>(w_proj, b_proj, out);
}

// round 3
// speedup vs baseline: 1.5980x; 1.5980x over previous
#include <cuda_runtime.h>
#include <cstdint>

// ---------------------------------------------------------------------------
// GroupAttention (Swin window attention)
// B=32, N=4096 (64x64), C=128, WS=8 -> G=64 windows, S=64 tokens/window
// heads=4, hd=32.
// Round 3: GEMMs via mma.sync tf32 (base-target PTX -> HMMA); attention fp32.
// (tcgen05 is unavailable: harness compiles PTX at target sm_103, not sm_103a)
// ---------------------------------------------------------------------------

#define B_    32
#define NTOK  4096
#define C_    128
#define G_    64
#define S_    64
#define NH    4
#define HD    32

// scratch (device globals; allocation-free)
__device__ float g_qkv[(size_t)B_ * G_ * S_ * 384];  // [B*G][S][384]
__device__ float g_att[(size_t)B_ * NTOK * C_];      // [B][N][C]

__device__ __forceinline__ int token_index(int g, int s) {
    return ((g >> 3) << 9) + ((s >> 3) << 6) + ((g & 7) << 3) + (s & 7);
}

__device__ __forceinline__ uint32_t f32_to_tf32(float x) {
    uint32_t r;
    asm("cvt.rna.tf32.f32 %0, %1;" : "=r"(r) : "f"(x));
    return r;
}

// D += A(16x8 row) * B(8x8 col)  tf32
__device__ __forceinline__ void mma_tf32(float* c, const uint32_t* a,
                                         const uint32_t* b) {
    asm volatile(
        "mma.sync.aligned.m16n8k8.row.col.f32.tf32.tf32.f32 "
        "{%0,%1,%2,%3}, {%4,%5,%6,%7}, {%8,%9}, {%0,%1,%2,%3};"
        : "+f"(c[0]), "+f"(c[1]), "+f"(c[2]), "+f"(c[3])
        : "r"(a[0]), "r"(a[1]), "r"(a[2]), "r"(a[3]), "r"(b[0]), "r"(b[1]));
}

// Shared tile: [128 rows][132 cols] of tf32 bits (pad kills bank conflicts)
#define LDA 132
#define SMEM_GEMM_BYTES (2 * 128 * LDA * 4)  // 135168

// ---------------------------------------------------------------------------
// Core 128x128x128 tf32 MMA tile. 256 threads = 8 warps, warp tile 32x64.
// As[r][k] (row-major K), Bs[o][k] (K contiguous) -> "row.col" mma.
// ---------------------------------------------------------------------------
struct Frag {
    float c[2][8][4];  // [mtile][ntile][reg]
};

__device__ __forceinline__ void mma_tile_compute(const uint32_t* As,
                                                 const uint32_t* Bs,
                                                 int m0, int n0, Frag& f) {
    const int lane = threadIdx.x & 31;
    const int lr = lane >> 2;      // 0..7
    const int lc = lane & 3;       // 0..3

    #pragma unroll
    for (int mi = 0; mi < 2; mi++)
        #pragma unroll
        for (int nj = 0; nj < 8; nj++)
            #pragma unroll
            for (int q = 0; q < 4; q++) f.c[mi][nj][q] = 0.f;

    #pragma unroll
    for (int k0 = 0; k0 < 128; k0 += 8) {
        uint32_t a[2][4];
        #pragma unroll
        for (int mi = 0; mi < 2; mi++) {
            const uint32_t* ap = As + (m0 + mi * 16 + lr) * LDA + k0 + lc;
            a[mi][0] = ap[0];
            a[mi][1] = ap[8 * LDA];
            a[mi][2] = ap[4];
            a[mi][3] = ap[8 * LDA + 4];
        }
        uint32_t b[8][2];
        #pragma unroll
        for (int nj = 0; nj < 8; nj++) {
            const uint32_t* bp = Bs + (n0 + nj * 8 + lr) * LDA + k0 + lc;
            b[nj][0] = bp[0];
            b[nj][1] = bp[4];
        }
        #pragma unroll
        for (int mi = 0; mi < 2; mi++)
            #pragma unroll
            for (int nj = 0; nj < 8; nj++)
                mma_tf32(f.c[mi][nj], a[mi], b[nj]);
    }
}

// ---------------------------- QKV GEMM ------------------------------------
// out[b,g,s,o] = sum_c x[b, n(g,s), c] * w_qkv[o, c]
// grid (3, 1024): x = o-tile, y = window pair. 256 threads.
__global__ void __launch_bounds__(256) qkv_mma(const float* __restrict__ x,
                                               const float* __restrict__ w) {
    extern __shared__ uint32_t smem[];
    uint32_t* As = smem;
    uint32_t* Bs = smem + 128 * LDA;

    const int tid = threadIdx.x;
    const int wid = tid >> 5, lane = tid & 31;
    const int o0 = blockIdx.x * 128;
    const int pair = blockIdx.y;
    const int b = pair >> 5;
    const int g0 = (pair & 31) << 1;

    // Load + convert to tf32
    #pragma unroll
    for (int it = 0; it < 16; it++) {
        int fidx = tid + it * 256;   // 0..4095 float4s
        int r = fidx >> 5;
        int c = (fidx & 31) << 2;
        int g = g0 + (r >> 6);
        int s = r & 63;
        int n = token_index(g, s);
        float4 v = *(const float4*)(x + ((size_t)b * NTOK + n) * C_ + c);
        uint4 t;
        t.x = f32_to_tf32(v.x); t.y = f32_to_tf32(v.y);
        t.z = f32_to_tf32(v.z); t.w = f32_to_tf32(v.w);
        *(uint4*)(As + r * LDA + c) = t;
    }
    #pragma unroll
    for (int it = 0; it < 16; it++) {
        int fidx = tid + it * 256;
        int r = fidx >> 5;
        int c = (fidx & 31) << 2;
        float4 v = *(const float4*)(w + (size_t)(o0 + r) * C_ + c);
        uint4 t;
        t.x = f32_to_tf32(v.x); t.y = f32_to_tf32(v.y);
        t.z = f32_to_tf32(v.z); t.w = f32_to_tf32(v.w);
        *(uint4*)(Bs + r * LDA + c) = t;
    }
    __syncthreads();

    const int m0 = (wid & 3) * 32;
    const int n0 = (wid >> 2) * 64;
    Frag f;
    mma_tile_compute(As, Bs, m0, n0, f);

    // Epilogue -> g_qkv[(b*64+g)*64+s][o0 + col]
    const int lr = lane >> 2, lc = lane & 3;
    #pragma unroll
    for (int mi = 0; mi < 2; mi++) {
        #pragma unroll
        for (int half = 0; half < 2; half++) {
            int r = m0 + mi * 16 + half * 8 + lr;
            int g = g0 + (r >> 6);
            int s = r & 63;
            float* orow = g_qkv + (((size_t)(b * G_ + g)) * S_ + s) * 384 + o0;
            #pragma unroll
            for (int nj = 0; nj < 8; nj++) {
                int col = n0 + nj * 8 + 2 * lc;
                float2 v = half ? make_float2(f.c[mi][nj][2], f.c[mi][nj][3])
                                : make_float2(f.c[mi][nj][0], f.c[mi][nj][1]);
                *(float2*)(orow + col) = v;
            }
        }
    }
}

// ---------------------------- proj GEMM -----------------------------------
__global__ void __launch_bounds__(256) proj_mma(const float* __restrict__ wp,
                                                const float* __restrict__ bp,
                                                float* __restrict__ out) {
    extern __shared__ uint32_t smem[];
    uint32_t* As = smem;
    uint32_t* Bs = smem + 128 * LDA;

    const int tid = threadIdx.x;
    const int wid = tid >> 5, lane = tid & 31;
    const size_t row0 = (size_t)blockIdx.x * 128;

    #pragma unroll
    for (int it = 0; it < 16; it++) {
        int fidx = tid + it * 256;
        int r = fidx >> 5;
        int c = (fidx & 31) << 2;
        float4 v = *(const float4*)(g_att + (row0 + r) * C_ + c);
        uint4 t;
        t.x = f32_to_tf32(v.x); t.y = f32_to_tf32(v.y);
        t.z = f32_to_tf32(v.z); t.w = f32_to_tf32(v.w);
        *(uint4*)(As + r * LDA + c) = t;
    }
    #pragma unroll
    for (int it = 0; it < 16; it++) {
        int fidx = tid + it * 256;
        int r = fidx >> 5;
        int c = (fidx & 31) << 2;
        float4 v = *(const float4*)(wp + (size_t)r * C_ + c);
        uint4 t;
        t.x = f32_to_tf32(v.x); t.y = f32_to_tf32(v.y);
        t.z = f32_to_tf32(v.z); t.w = f32_to_tf32(v.w);
        *(uint4*)(Bs + r * LDA + c) = t;
    }
    __syncthreads();

    const int m0 = (wid & 3) * 32;
    const int n0 = (wid >> 2) * 64;
    Frag f;
    mma_tile_compute(As, Bs, m0, n0, f);

    const int lr = lane >> 2, lc = lane & 3;
    #pragma unroll
    for (int mi = 0; mi < 2; mi++) {
        #pragma unroll
        for (int half = 0; half < 2; half++) {
            size_t r = row0 + m0 + mi * 16 + half * 8 + lr;
            float* orow = out + r * C_;
            #pragma unroll
            for (int nj = 0; nj < 8; nj++) {
                int col = n0 + nj * 8 + 2 * lc;
                float2 v = half ? make_float2(f.c[mi][nj][2], f.c[mi][nj][3])
                                : make_float2(f.c[mi][nj][0], f.c[mi][nj][1]);
                v.x += bp[col];
                v.y += bp[col + 1];
                *(float2*)(orow + col) = v;
            }
        }
    }
}

// ---------------------------------------------------------------------------
// Window attention (fp32): one block per (b,g). 256 threads = 4 heads x 64 s.
// ---------------------------------------------------------------------------
__global__ void __launch_bounds__(256) attn_kernel() {
    extern __shared__ float sh[];  // [64][388]
    const int tid = threadIdx.x;
    const int bg = blockIdx.x;

    const float* base = g_qkv + (size_t)bg * (S_ * 384);
    #pragma unroll
    for (int it = 0; it < 24; it++) {
        int fidx = tid + it * 256;
        int r = fidx / 96;
        int c4 = fidx % 96;
        *(float4*)(sh + r * 388 + c4 * 4) =
            *(const float4*)(base + r * 384 + c4 * 4);
    }
    __syncthreads();

    const int head = tid >> 6;
    const int s = tid & 63;
    const int hb = head * HD;
    const float scale = 0.1767766952966369f;

    float4 q4[8];
    #pragma unroll
    for (int d4 = 0; d4 < 8; d4++)
        q4[d4] = *(const float4*)(sh + s * 388 + hb + 4 * d4);

    float att[64];
    float mx = -1e30f;
    #pragma unroll
    for (int t = 0; t < 64; t++) {
        const float* kr = sh + t * 388 + 128 + hb;
        float s0 = 0.f, s1 = 0.f, s2 = 0.f, s3 = 0.f;
        #pragma unroll
        for (int d4 = 0; d4 < 8; d4++) {
            float4 k4 = *(const float4*)(kr + 4 * d4);
            s0 += q4[d4].x * k4.x;
            s1 += q4[d4].y * k4.y;
            s2 += q4[d4].z * k4.z;
            s3 += q4[d4].w * k4.w;
        }
        float a = (s0 + s1) + (s2 + s3);
        att[t] = a;
        mx = fmaxf(mx, a);
    }

    float sum = 0.f;
    float4 o4[8];
    #pragma unroll
    for (int d4 = 0; d4 < 8; d4++) o4[d4] = make_float4(0.f, 0.f, 0.f, 0.f);

    #pragma unroll
    for (int t = 0; t < 64; t++) {
        float e = __expf((att[t] - mx) * scale);
        sum += e;
        const float* vr = sh + t * 388 + 256 + hb;
        #pragma unroll
        for (int d4 = 0; d4 < 8; d4++) {
            float4 v4 = *(const float4*)(vr + 4 * d4);
            o4[d4].x += e * v4.x;
            o4[d4].y += e * v4.y;
            o4[d4].z += e * v4.z;
            o4[d4].w += e * v4.w;
        }
    }
    float inv = 1.f / sum;

    const int b = bg >> 6, g = bg & 63;
    const int n = token_index(g, s);
    float* orow = g_att + ((size_t)b * NTOK + n) * C_ + hb;
    #pragma unroll
    for (int d4 = 0; d4 < 8; d4++) {
        float4 v = o4[d4];
        v.x *= inv; v.y *= inv; v.z *= inv; v.w *= inv;
        *(float4*)(orow + 4 * d4) = v;
    }
}

// ---------------------------------------------------------------------------
extern "C" void kernel_launch(void* const* d_in, const int* in_sizes, int n_in,
                              void* d_out, int out_size) {
    (void)in_sizes; (void)n_in; (void)out_size;
    const float* x      = (const float*)d_in[0];
    const float* w_qkv  = (const float*)d_in[1];
    const float* w_proj = (const float*)d_in[2];
    const float* b_proj = (const float*)d_in[3];
    float* out = (float*)d_out;

    const int SMEM_ATTN = 64 * 388 * 4;  // 99328
    cudaFuncSetAttribute(qkv_mma,  cudaFuncAttributeMaxDynamicSharedMemorySize, SMEM_GEMM_BYTES);
    cudaFuncSetAttribute(proj_mma, cudaFuncAttributeMaxDynamicSharedMemorySize, SMEM_GEMM_BYTES);
    cudaFuncSetAttribute(attn_kernel, cudaFuncAttributeMaxDynamicSharedMemorySize, SMEM_ATTN);

    qkv_mma<<<dim3(3, 1024), 256, SMEM_GEMM_BYTES>>>(x, w_qkv);
    attn_kernel<<<B_ * G_, 256, SMEM_ATTN>>>();
    proj_mma<<<1024, 256, SMEM_GEMM_BYTES>>>(w_proj, b_proj, out);
}

// round 5
// speedup vs baseline: 4.6585x; 2.9152x over previous
#include <cuda_runtime.h>
#include <cuda_fp16.h>
#include <cstdint>

// ---------------------------------------------------------------------------
// GroupAttention (Swin window attention)
// B=32, N=4096 (64x64), C=128, WS=8 -> G=64 windows, S=64 tokens/window
// heads=4, hd=32.
// Round 5: round-4 fused design with the proj warp-coverage bug fixed
// (proj warp tile is 32x64 again; round 4 left rows 64..127 unwritten).
// ---------------------------------------------------------------------------

#define B_    32
#define NTOK  4096
#define C_    128
#define G_    64
#define S_    64
#define NH    4
#define HD    32

// attention output, fp16, un-windowed [B][N][C] layout for the proj GEMM
__device__ __half g_att_h[(size_t)B_ * NTOK * C_];

__device__ __forceinline__ int token_index(int g, int s) {
    return ((g >> 3) << 9) + ((s >> 3) << 6) + ((g & 7) << 3) + (s & 7);
}

__device__ __forceinline__ uint32_t h2u(__half2 h) {
    return *(uint32_t*)&h;
}

// D += A(16x16 row, fp16) * B(16x8 col, fp16), fp32 accum
__device__ __forceinline__ void mma_f16(float* c, const uint32_t* a,
                                        const uint32_t* b) {
    asm volatile(
        "mma.sync.aligned.m16n8k16.row.col.f32.f16.f16.f32 "
        "{%0,%1,%2,%3}, {%4,%5,%6,%7}, {%8,%9}, {%0,%1,%2,%3};"
        : "+f"(c[0]), "+f"(c[1]), "+f"(c[2]), "+f"(c[3])
        : "r"(a[0]), "r"(a[1]), "r"(a[2]), "r"(a[3]), "r"(b[0]), "r"(b[1]));
}

// smem strides (word-stride % 32 == 4: conflict-free fragment LDS)
#define LDH 136   // halfwords per row for 128-col tiles (68 words)
#define LDW 68
#define VLDH 72   // Vt rows are 64 tokens wide, pad to 72 halves (36 words)
#define VLDW 36

#define OFF_X  0                      // Xs [64][136] fp16 : 17408
#define OFF_W  17408                  // Ws [128][136]     : 34816
#define OFF_Q  52224                  // Qh [64][136]      : 17408
#define OFF_K  69632                  // Kh [64][136]      : 17408
#define OFF_V  87040                  // Vt [128][72]      : 18432
#define SMEM_FUSED 105472

#define SCALE 0.17677669529663687f

// ---------------------------------------------------------------------------
// Fused QKV + window attention. One block per (b, g) window. 256 threads.
// ---------------------------------------------------------------------------
__global__ void __launch_bounds__(256, 2)
fused_qkv_attn(const float* __restrict__ x, const float* __restrict__ w) {
    extern __shared__ char sm[];
    __half* Xs = (__half*)(sm + OFF_X);
    __half* Ws = (__half*)(sm + OFF_W);
    __half* Qh = (__half*)(sm + OFF_Q);
    __half* Kh = (__half*)(sm + OFF_K);
    __half* Vt = (__half*)(sm + OFF_V);
    const uint32_t* Xw = (const uint32_t*)Xs;
    const uint32_t* Ww = (const uint32_t*)Ws;
    const uint32_t* Qw = (const uint32_t*)Qh;
    const uint32_t* Kw = (const uint32_t*)Kh;
    const uint32_t* Vw = (const uint32_t*)Vt;

    const int tid = threadIdx.x;
    const int wid = tid >> 5, lane = tid & 31;
    const int lr = lane >> 2, lc = lane & 3;
    const int bg = blockIdx.x;
    const int b = bg >> 6, g = bg & 63;

    // ---- load x window (gathered) as fp16 ----
    #pragma unroll
    for (int it = 0; it < 8; it++) {
        int fidx = tid + it * 256;           // 2048 float4s: 64 rows x 32
        int s = fidx >> 5;
        int c4 = fidx & 31;
        int n = token_index(g, s);
        float4 v = *(const float4*)(x + ((size_t)b * NTOK + n) * C_ + c4 * 4);
        __half2* dst = (__half2*)(Xs + s * LDH + c4 * 4);
        dst[0] = __floats2half2_rn(v.x, v.y);
        dst[1] = __floats2half2_rn(v.z, v.w);
    }

    // ---- QKV GEMM: 3 chunks of 128 output features ----
    const int m0 = (wid & 3) * 16;
    const int n0 = (wid >> 2) * 64;

    #pragma unroll
    for (int ch = 0; ch < 3; ch++) {
        __syncthreads();   // prev chunk's mma reads of Ws done; Xs fill ordered
        #pragma unroll
        for (int it = 0; it < 16; it++) {
            int fidx = tid + it * 256;       // 4096 float4s: 128 rows x 32
            int r = fidx >> 5;
            int c4 = fidx & 31;
            float4 v = *(const float4*)(w + (size_t)(ch * 128 + r) * C_ + c4 * 4);
            __half2* dst = (__half2*)(Ws + r * LDH + c4 * 4);
            dst[0] = __floats2half2_rn(v.x, v.y);
            dst[1] = __floats2half2_rn(v.z, v.w);
        }
        __syncthreads();

        float c[8][4];
        #pragma unroll
        for (int nj = 0; nj < 8; nj++)
            #pragma unroll
            for (int q = 0; q < 4; q++) c[nj][q] = 0.f;

        #pragma unroll
        for (int kt = 0; kt < 8; kt++) {
            uint32_t a[4];
            int abase = (m0 + lr) * LDW + kt * 8 + lc;
            a[0] = Xw[abase];
            a[1] = Xw[abase + 8 * LDW];
            a[2] = Xw[abase + 4];
            a[3] = Xw[abase + 8 * LDW + 4];
            #pragma unroll
            for (int nj = 0; nj < 8; nj++) {
                uint32_t bfr[2];
                int bbase = (n0 + nj * 8 + lr) * LDW + kt * 8 + lc;
                bfr[0] = Ww[bbase];
                bfr[1] = Ww[bbase + 4];
                mma_f16(c[nj], a, bfr);
            }
        }

        // epilogue: q -> Qh, k -> Kh, v -> Vt (transposed)
        if (ch == 0 || ch == 1) {
            __half* Th = (ch == 0) ? Qh : Kh;
            #pragma unroll
            for (int nj = 0; nj < 8; nj++) {
                int col = n0 + nj * 8 + 2 * lc;
                *(__half2*)(Th + (m0 + lr) * LDH + col) =
                    __floats2half2_rn(c[nj][0], c[nj][1]);
                *(__half2*)(Th + (m0 + lr + 8) * LDH + col) =
                    __floats2half2_rn(c[nj][2], c[nj][3]);
            }
        } else {
            #pragma unroll
            for (int nj = 0; nj < 8; nj++) {
                int d = n0 + nj * 8 + 2 * lc;
                int s0 = m0 + lr;
                Vt[d * VLDH + s0]           = __float2half_rn(c[nj][0]);
                Vt[(d + 1) * VLDH + s0]     = __float2half_rn(c[nj][1]);
                Vt[d * VLDH + s0 + 8]       = __float2half_rn(c[nj][2]);
                Vt[(d + 1) * VLDH + s0 + 8] = __float2half_rn(c[nj][3]);
            }
        }
    }
    __syncthreads();

    // ---- attention: head = wid>>1, rows m0a..m0a+31 ----
    const int head = wid >> 1;
    const int hw = head * 16;          // word offset of head features
    const int hb = head * 32;
    const int m0a = (wid & 1) * 32;

    // S = Q K^T  (scores, fp32 frags)
    float sf[2][8][4];
    #pragma unroll
    for (int mi = 0; mi < 2; mi++)
        #pragma unroll
        for (int nj = 0; nj < 8; nj++)
            #pragma unroll
            for (int q = 0; q < 4; q++) sf[mi][nj][q] = 0.f;

    #pragma unroll
    for (int kt = 0; kt < 2; kt++) {
        uint32_t a[2][4];
        #pragma unroll
        for (int mi = 0; mi < 2; mi++) {
            int abase = (m0a + mi * 16 + lr) * LDW + hw + kt * 8 + lc;
            a[mi][0] = Qw[abase];
            a[mi][1] = Qw[abase + 8 * LDW];
            a[mi][2] = Qw[abase + 4];
            a[mi][3] = Qw[abase + 8 * LDW + 4];
        }
        #pragma unroll
        for (int nj = 0; nj < 8; nj++) {
            uint32_t bfr[2];
            int bbase = (nj * 8 + lr) * LDW + hw + kt * 8 + lc;
            bfr[0] = Kw[bbase];
            bfr[1] = Kw[bbase + 4];
            mma_f16(sf[0][nj], a[0], bfr);
            mma_f16(sf[1][nj], a[1], bfr);
        }
    }

    // softmax over the 64 columns, rows distributed (lr: lo, lr+8: hi)
    float invlo[2], invhi[2];
    uint32_t ph[2][8][2];
    #pragma unroll
    for (int mi = 0; mi < 2; mi++) {
        float mlo = -1e30f, mhi = -1e30f;
        #pragma unroll
        for (int nj = 0; nj < 8; nj++) {
            mlo = fmaxf(mlo, fmaxf(sf[mi][nj][0], sf[mi][nj][1]));
            mhi = fmaxf(mhi, fmaxf(sf[mi][nj][2], sf[mi][nj][3]));
        }
        mlo = fmaxf(mlo, __shfl_xor_sync(0xffffffffu, mlo, 1));
        mlo = fmaxf(mlo, __shfl_xor_sync(0xffffffffu, mlo, 2));
        mhi = fmaxf(mhi, __shfl_xor_sync(0xffffffffu, mhi, 1));
        mhi = fmaxf(mhi, __shfl_xor_sync(0xffffffffu, mhi, 2));

        float slo = 0.f, shi = 0.f;
        #pragma unroll
        for (int nj = 0; nj < 8; nj++) {
            float e0 = __expf((sf[mi][nj][0] - mlo) * SCALE);
            float e1 = __expf((sf[mi][nj][1] - mlo) * SCALE);
            float e2 = __expf((sf[mi][nj][2] - mhi) * SCALE);
            float e3 = __expf((sf[mi][nj][3] - mhi) * SCALE);
            slo += e0 + e1;
            shi += e2 + e3;
            ph[mi][nj][0] = h2u(__floats2half2_rn(e0, e1));
            ph[mi][nj][1] = h2u(__floats2half2_rn(e2, e3));
        }
        slo += __shfl_xor_sync(0xffffffffu, slo, 1);
        slo += __shfl_xor_sync(0xffffffffu, slo, 2);
        shi += __shfl_xor_sync(0xffffffffu, shi, 1);
        shi += __shfl_xor_sync(0xffffffffu, shi, 2);
        invlo[mi] = 1.f / slo;
        invhi[mi] = 1.f / shi;
    }

    // O = P V  (P frags reused directly as A operands)
    float o[2][4][4];
    #pragma unroll
    for (int mi = 0; mi < 2; mi++)
        #pragma unroll
        for (int nj = 0; nj < 4; nj++)
            #pragma unroll
            for (int q = 0; q < 4; q++) o[mi][nj][q] = 0.f;

    #pragma unroll
    for (int kt = 0; kt < 4; kt++) {
        uint32_t a[2][4];
        #pragma unroll
        for (int mi = 0; mi < 2; mi++) {
            a[mi][0] = ph[mi][2 * kt][0];
            a[mi][1] = ph[mi][2 * kt][1];
            a[mi][2] = ph[mi][2 * kt + 1][0];
            a[mi][3] = ph[mi][2 * kt + 1][1];
        }
        #pragma unroll
        for (int nj = 0; nj < 4; nj++) {
            uint32_t bfr[2];
            int bbase = (hb + nj * 8 + lr) * VLDW + kt * 8 + lc;
            bfr[0] = Vw[bbase];
            bfr[1] = Vw[bbase + 4];
            mma_f16(o[0][nj], a[0], bfr);
            mma_f16(o[1][nj], a[1], bfr);
        }
    }

    // normalize + store fp16 to un-windowed [B][N][C]
    #pragma unroll
    for (int mi = 0; mi < 2; mi++) {
        int s0 = m0a + mi * 16 + lr;
        int n0t = token_index(g, s0);
        int n1t = token_index(g, s0 + 8);
        __half* r0 = g_att_h + ((size_t)b * NTOK + n0t) * C_ + hb;
        __half* r1 = g_att_h + ((size_t)b * NTOK + n1t) * C_ + hb;
        #pragma unroll
        for (int nj = 0; nj < 4; nj++) {
            int d = nj * 8 + 2 * lc;
            *(__half2*)(r0 + d) = __floats2half2_rn(o[mi][nj][0] * invlo[mi],
                                                    o[mi][nj][1] * invlo[mi]);
            *(__half2*)(r1 + d) = __floats2half2_rn(o[mi][nj][2] * invhi[mi],
                                                    o[mi][nj][3] * invhi[mi]);
        }
    }
}

// ---------------------------------------------------------------------------
// Output projection, fp16 mma: out[row,o] = sum_c att[row,c]*wp[o,c] + bp[o]
// Block tile 128x128; warp tile 32x64 (full row coverage — round-4 fix).
// ---------------------------------------------------------------------------
#define PROJ_SMEM (2 * 128 * LDH * 2)   // 69632

__global__ void __launch_bounds__(256)
proj_mma(const float* __restrict__ wp, const float* __restrict__ bp,
         float* __restrict__ out) {
    extern __shared__ char sm[];
    __half* Ash = (__half*)sm;                    // [128][136]
    __half* Bsh = (__half*)(sm + 128 * LDH * 2);  // [128][136]
    const uint32_t* Aw = (const uint32_t*)Ash;
    const uint32_t* Bw = (const uint32_t*)Bsh;

    const int tid = threadIdx.x;
    const int wid = tid >> 5, lane = tid & 31;
    const int lr = lane >> 2, lc = lane & 3;
    const size_t row0 = (size_t)blockIdx.x * 128;

    // A: fp16 rows straight from g_att_h
    #pragma unroll
    for (int it = 0; it < 8; it++) {
        int fidx = tid + it * 256;     // 2048 uint4s: 128 rows x 16
        int r = fidx >> 4;
        int q = fidx & 15;
        uint4 v = *(const uint4*)(g_att_h + (row0 + r) * C_ + q * 8);
        *(uint4*)(Ash + r * LDH + q * 8) = v;
    }
    // B: w_proj fp32 -> fp16
    #pragma unroll
    for (int it = 0; it < 16; it++) {
        int fidx = tid + it * 256;     // 4096 float4s
        int r = fidx >> 5;
        int c4 = fidx & 31;
        float4 v = *(const float4*)(wp + (size_t)r * C_ + c4 * 4);
        __half2* dst = (__half2*)(Bsh + r * LDH + c4 * 4);
        dst[0] = __floats2half2_rn(v.x, v.y);
        dst[1] = __floats2half2_rn(v.z, v.w);
    }
    __syncthreads();

    const int m0 = (wid & 3) * 32;     // 32-row warp tile: full 128 rows
    const int n0 = (wid >> 2) * 64;

    float c[2][8][4];
    #pragma unroll
    for (int mi = 0; mi < 2; mi++)
        #pragma unroll
        for (int nj = 0; nj < 8; nj++)
            #pragma unroll
            for (int q = 0; q < 4; q++) c[mi][nj][q] = 0.f;

    #pragma unroll
    for (int kt = 0; kt < 8; kt++) {
        uint32_t a[2][4];
        #pragma unroll
        for (int mi = 0; mi < 2; mi++) {
            int abase = (m0 + mi * 16 + lr) * LDW + kt * 8 + lc;
            a[mi][0] = Aw[abase];
            a[mi][1] = Aw[abase + 8 * LDW];
            a[mi][2] = Aw[abase + 4];
            a[mi][3] = Aw[abase + 8 * LDW + 4];
        }
        #pragma unroll
        for (int nj = 0; nj < 8; nj++) {
            uint32_t bfr[2];
            int bbase = (n0 + nj * 8 + lr) * LDW + kt * 8 + lc;
            bfr[0] = Bw[bbase];
            bfr[1] = Bw[bbase + 4];
            mma_f16(c[0][nj], a[0], bfr);
            mma_f16(c[1][nj], a[1], bfr);
        }
    }

    #pragma unroll
    for (int mi = 0; mi < 2; mi++) {
        #pragma unroll
        for (int nj = 0; nj < 8; nj++) {
            int col = n0 + nj * 8 + 2 * lc;
            float bx = bp[col], by = bp[col + 1];
            float* r0 = out + (row0 + m0 + mi * 16 + lr) * C_ + col;
            float* r1 = out + (row0 + m0 + mi * 16 + lr + 8) * C_ + col;
            *(float2*)r0 = make_float2(c[mi][nj][0] + bx, c[mi][nj][1] + by);
            *(float2*)r1 = make_float2(c[mi][nj][2] + bx, c[mi][nj][3] + by);
        }
    }
}

// ---------------------------------------------------------------------------
extern "C" void kernel_launch(void* const* d_in, const int* in_sizes, int n_in,
                              void* d_out, int out_size) {
    (void)in_sizes; (void)n_in; (void)out_size;
    const float* x      = (const float*)d_in[0];
    const float* w_qkv  = (const float*)d_in[1];
    const float* w_proj = (const float*)d_in[2];
    const float* b_proj = (const float*)d_in[3];
    float* out = (float*)d_out;

    cudaFuncSetAttribute(fused_qkv_attn,
                         cudaFuncAttributeMaxDynamicSharedMemorySize, SMEM_FUSED);
    cudaFuncSetAttribute(proj_mma,
                         cudaFuncAttributeMaxDynamicSharedMemorySize, PROJ_SMEM);

    fused_qkv_attn<<<B_ * G_, 256, SMEM_FUSED>>>(x, w_qkv);
    proj_mma<<<1024, 256, PROJ_SMEM>>>(w_proj, b_proj, out);
}

// round 6
// speedup vs baseline: 5.4736x; 1.1750x over previous
#include <cuda_runtime.h>
#include <cuda_fp16.h>
#include <cstdint>

// ---------------------------------------------------------------------------
// GroupAttention (Swin window attention)
// B=32, N=4096 (64x64), C=128, WS=8 -> G=64 windows, S=64 tokens/window
// heads=4, hd=32.
// Round 6: ONE fully-fused kernel (QKV + attention + proj), 2 windows/CTA,
// 512 threads, fp16 weights pre-converted once. No big global intermediates.
// ---------------------------------------------------------------------------

#define B_    32
#define NTOK  4096
#define C_    128
#define G_    64
#define S_    64
#define NH    4
#define HD    32

// fp16 weight copies (tiny; written once by cvt_weights)
__device__ __half g_wq_h[384 * 128];
__device__ __half g_wp_h[128 * 128];

__device__ __forceinline__ int token_index(int g, int s) {
    return ((g >> 3) << 9) + ((s >> 3) << 6) + ((g & 7) << 3) + (s & 7);
}

__device__ __forceinline__ uint32_t h2u(__half2 h) {
    return *(uint32_t*)&h;
}

__device__ __forceinline__ void mma_f16(float* c, const uint32_t* a,
                                        const uint32_t* b) {
    asm volatile(
        "mma.sync.aligned.m16n8k16.row.col.f32.f16.f16.f32 "
        "{%0,%1,%2,%3}, {%4,%5,%6,%7}, {%8,%9}, {%0,%1,%2,%3};"
        : "+f"(c[0]), "+f"(c[1]), "+f"(c[2]), "+f"(c[3])
        : "r"(a[0]), "r"(a[1]), "r"(a[2]), "r"(a[3]), "r"(b[0]), "r"(b[1]));
}

// smem strides (word-stride % 32 == 4: conflict-free fragment LDS)
#define LDH 136
#define LDW 68
#define VLDH 72
#define VLDW 36

// byte offsets; Xs doubles as O after the QKV phase
#define OFF_X  0                        // Xs/Oh [128][136] : 34816
#define OFF_W  34816                    // Ws    [128][136] : 34816
#define OFF_Q  69632                    // Qh    [128][136] : 34816
#define OFF_K  104448                   // Kh    [128][136] : 34816
#define OFF_V  139264                   // Vt  2x[128][72]  : 36864
#define VT_BYTES 18432
#define SMEM_FUSED 176128

#define SCALE 0.17677669529663687f

// ---------------------------------------------------------------------------
// Prepass: fp32 weights -> fp16 device globals. 64 blocks x 256 threads.
// ---------------------------------------------------------------------------
__global__ void __launch_bounds__(256) cvt_weights(const float* __restrict__ wq,
                                                   const float* __restrict__ wp) {
    int idx = blockIdx.x * 256 + threadIdx.x;    // 16384 float4 slots
    if (idx < 12288) {                           // w_qkv: 49152 floats
        float4 v = ((const float4*)wq)[idx];
        __half2* d = (__half2*)g_wq_h + idx * 2;
        d[0] = __floats2half2_rn(v.x, v.y);
        d[1] = __floats2half2_rn(v.z, v.w);
    } else {                                     // w_proj: 16384 floats
        int j = idx - 12288;
        float4 v = ((const float4*)wp)[j];
        __half2* d = (__half2*)g_wp_h + j * 2;
        d[0] = __floats2half2_rn(v.x, v.y);
        d[1] = __floats2half2_rn(v.z, v.w);
    }
}

// ---------------------------------------------------------------------------
// Fully fused kernel. One block per 2 windows. 512 threads (16 warps).
// ---------------------------------------------------------------------------
__global__ void __launch_bounds__(512, 1)
fused_all(const float* __restrict__ x, const float* __restrict__ bp,
          float* __restrict__ out) {
    extern __shared__ char sm[];
    __half* Xs = (__half*)(sm + OFF_X);       // also O buffer later
    __half* Ws = (__half*)(sm + OFF_W);
    __half* Qh = (__half*)(sm + OFF_Q);
    __half* Kh = (__half*)(sm + OFF_K);
    const uint32_t* Xw = (const uint32_t*)Xs;
    const uint32_t* Ww = (const uint32_t*)Ws;
    const uint32_t* Qw = (const uint32_t*)Qh;
    const uint32_t* Kw = (const uint32_t*)Kh;

    const int tid = threadIdx.x;
    const int wid = tid >> 5, lane = tid & 31;
    const int lr = lane >> 2, lc = lane & 3;
    const int bg = blockIdx.x;                 // 0..1023
    const int b = bg >> 5;
    const int g0 = (bg & 31) << 1;             // two consecutive windows

    // ---- load x: 2 windows, 128 rows, fp32 -> fp16 ----
    #pragma unroll
    for (int it = 0; it < 8; it++) {
        int fidx = tid + it * 512;             // 4096 float4s
        int r = fidx >> 5;                     // 0..127
        int c4 = fidx & 31;
        int n = token_index(g0 + (r >> 6), r & 63);
        float4 v = *(const float4*)(x + ((size_t)b * NTOK + n) * C_ + c4 * 4);
        __half2* dst = (__half2*)(Xs + r * LDH + c4 * 4);
        dst[0] = __floats2half2_rn(v.x, v.y);
        dst[1] = __floats2half2_rn(v.z, v.w);
    }

    // ---- QKV GEMM: M=128 (2 windows) x N=128, 3 chunks; warp tile 32x32 ----
    const int m0 = (wid & 3) * 32;
    const int n0 = (wid >> 2) * 32;

    #pragma unroll
    for (int ch = 0; ch < 3; ch++) {
        __syncthreads();                       // Ws free; X ready (ch 0)
        #pragma unroll
        for (int it = 0; it < 4; it++) {
            int fidx = tid + it * 512;         // 2048 uint4s: 128 rows x 16
            int r = fidx >> 4;
            int q = fidx & 15;
            uint4 v = *(const uint4*)(g_wq_h + (size_t)(ch * 128 + r) * C_ + q * 8);
            *(uint4*)(Ws + r * LDH + q * 8) = v;
        }
        __syncthreads();

        float c[2][4][4];
        #pragma unroll
        for (int mi = 0; mi < 2; mi++)
            #pragma unroll
            for (int nj = 0; nj < 4; nj++)
                #pragma unroll
                for (int q = 0; q < 4; q++) c[mi][nj][q] = 0.f;

        #pragma unroll
        for (int kt = 0; kt < 8; kt++) {
            uint32_t a[2][4];
            #pragma unroll
            for (int mi = 0; mi < 2; mi++) {
                int abase = (m0 + mi * 16 + lr) * LDW + kt * 8 + lc;
                a[mi][0] = Xw[abase];
                a[mi][1] = Xw[abase + 8 * LDW];
                a[mi][2] = Xw[abase + 4];
                a[mi][3] = Xw[abase + 8 * LDW + 4];
            }
            #pragma unroll
            for (int nj = 0; nj < 4; nj++) {
                uint32_t bfr[2];
                int bbase = (n0 + nj * 8 + lr) * LDW + kt * 8 + lc;
                bfr[0] = Ww[bbase];
                bfr[1] = Ww[bbase + 4];
                mma_f16(c[0][nj], a[0], bfr);
                mma_f16(c[1][nj], a[1], bfr);
            }
        }

        // epilogue: ch0 -> Qh, ch1 -> Kh, ch2 -> Vt (transposed, per window)
        if (ch < 2) {
            __half* Th = (ch == 0) ? Qh : Kh;
            #pragma unroll
            for (int mi = 0; mi < 2; mi++)
                #pragma unroll
                for (int nj = 0; nj < 4; nj++) {
                    int col = n0 + nj * 8 + 2 * lc;
                    int r = m0 + mi * 16 + lr;
                    *(__half2*)(Th + r * LDH + col) =
                        __floats2half2_rn(c[mi][nj][0], c[mi][nj][1]);
                    *(__half2*)(Th + (r + 8) * LDH + col) =
                        __floats2half2_rn(c[mi][nj][2], c[mi][nj][3]);
                }
        } else {
            #pragma unroll
            for (int mi = 0; mi < 2; mi++)
                #pragma unroll
                for (int nj = 0; nj < 4; nj++) {
                    int r = m0 + mi * 16 + lr;
                    int win = r >> 6;
                    int s0 = r & 63;
                    __half* V = (__half*)(sm + OFF_V + win * VT_BYTES);
                    int d = n0 + nj * 8 + 2 * lc;
                    V[d * VLDH + s0]           = __float2half_rn(c[mi][nj][0]);
                    V[(d + 1) * VLDH + s0]     = __float2half_rn(c[mi][nj][1]);
                    V[d * VLDH + s0 + 8]       = __float2half_rn(c[mi][nj][2]);
                    V[(d + 1) * VLDH + s0 + 8] = __float2half_rn(c[mi][nj][3]);
                }
        }
    }
    __syncthreads();   // Q/K/Vt complete; Xs & Ws now reusable

    // ---- preload Wp into Ws (overlaps with attention math) ----
    #pragma unroll
    for (int it = 0; it < 4; it++) {
        int fidx = tid + it * 512;
        int r = fidx >> 4;
        int q = fidx & 15;
        uint4 v = *(const uint4*)(g_wp_h + (size_t)r * C_ + q * 8);
        *(uint4*)(Ws + r * LDH + q * 8) = v;
    }

    // ---- attention: warp = (win, head, row-half). 16 warps = 2*4*2 ----
    const int win = wid >> 3;
    const int head = (wid >> 1) & 3;
    const int hw = head * 16;          // word offset of head within row
    const int hb = head * 32;          // half offset
    const int m0a = (wid & 1) * 32;
    const int rbase = win * 64;
    const uint32_t* Vw = (const uint32_t*)(sm + OFF_V + win * VT_BYTES);

    // S = Q K^T
    float sf[2][8][4];
    #pragma unroll
    for (int mi = 0; mi < 2; mi++)
        #pragma unroll
        for (int nj = 0; nj < 8; nj++)
            #pragma unroll
            for (int q = 0; q < 4; q++) sf[mi][nj][q] = 0.f;

    #pragma unroll
    for (int kt = 0; kt < 2; kt++) {
        uint32_t a[2][4];
        #pragma unroll
        for (int mi = 0; mi < 2; mi++) {
            int abase = (rbase + m0a + mi * 16 + lr) * LDW + hw + kt * 8 + lc;
            a[mi][0] = Qw[abase];
            a[mi][1] = Qw[abase + 8 * LDW];
            a[mi][2] = Qw[abase + 4];
            a[mi][3] = Qw[abase + 8 * LDW + 4];
        }
        #pragma unroll
        for (int nj = 0; nj < 8; nj++) {
            uint32_t bfr[2];
            int bbase = (rbase + nj * 8 + lr) * LDW + hw + kt * 8 + lc;
            bfr[0] = Kw[bbase];
            bfr[1] = Kw[bbase + 4];
            mma_f16(sf[0][nj], a[0], bfr);
            mma_f16(sf[1][nj], a[1], bfr);
        }
    }

    // softmax (rows lr: lo, lr+8: hi within each 16-row group)
    float invlo[2], invhi[2];
    uint32_t ph[2][8][2];
    #pragma unroll
    for (int mi = 0; mi < 2; mi++) {
        float mlo = -1e30f, mhi = -1e30f;
        #pragma unroll
        for (int nj = 0; nj < 8; nj++) {
            mlo = fmaxf(mlo, fmaxf(sf[mi][nj][0], sf[mi][nj][1]));
            mhi = fmaxf(mhi, fmaxf(sf[mi][nj][2], sf[mi][nj][3]));
        }
        mlo = fmaxf(mlo, __shfl_xor_sync(0xffffffffu, mlo, 1));
        mlo = fmaxf(mlo, __shfl_xor_sync(0xffffffffu, mlo, 2));
        mhi = fmaxf(mhi, __shfl_xor_sync(0xffffffffu, mhi, 1));
        mhi = fmaxf(mhi, __shfl_xor_sync(0xffffffffu, mhi, 2));

        float slo = 0.f, shi = 0.f;
        #pragma unroll
        for (int nj = 0; nj < 8; nj++) {
            float e0 = __expf((sf[mi][nj][0] - mlo) * SCALE);
            float e1 = __expf((sf[mi][nj][1] - mlo) * SCALE);
            float e2 = __expf((sf[mi][nj][2] - mhi) * SCALE);
            float e3 = __expf((sf[mi][nj][3] - mhi) * SCALE);
            slo += e0 + e1;
            shi += e2 + e3;
            ph[mi][nj][0] = h2u(__floats2half2_rn(e0, e1));
            ph[mi][nj][1] = h2u(__floats2half2_rn(e2, e3));
        }
        slo += __shfl_xor_sync(0xffffffffu, slo, 1);
        slo += __shfl_xor_sync(0xffffffffu, slo, 2);
        shi += __shfl_xor_sync(0xffffffffu, shi, 1);
        shi += __shfl_xor_sync(0xffffffffu, shi, 2);
        invlo[mi] = 1.f / slo;
        invhi[mi] = 1.f / shi;
    }

    // O = P V
    float o[2][4][4];
    #pragma unroll
    for (int mi = 0; mi < 2; mi++)
        #pragma unroll
        for (int nj = 0; nj < 4; nj++)
            #pragma unroll
            for (int q = 0; q < 4; q++) o[mi][nj][q] = 0.f;

    #pragma unroll
    for (int kt = 0; kt < 4; kt++) {
        uint32_t a[2][4];
        #pragma unroll
        for (int mi = 0; mi < 2; mi++) {
            a[mi][0] = ph[mi][2 * kt][0];
            a[mi][1] = ph[mi][2 * kt][1];
            a[mi][2] = ph[mi][2 * kt + 1][0];
            a[mi][3] = ph[mi][2 * kt + 1][1];
        }
        #pragma unroll
        for (int nj = 0; nj < 4; nj++) {
            uint32_t bfr[2];
            int bbase = (hb + nj * 8 + lr) * VLDW + kt * 8 + lc;
            bfr[0] = Vw[bbase];
            bfr[1] = Vw[bbase + 4];
            mma_f16(o[0][nj], a[0], bfr);
            mma_f16(o[1][nj], a[1], bfr);
        }
    }

    // normalize, store O into Xs buffer (windowed row order)
    __half* Oh = Xs;
    #pragma unroll
    for (int mi = 0; mi < 2; mi++) {
        int r = rbase + m0a + mi * 16 + lr;
        #pragma unroll
        for (int nj = 0; nj < 4; nj++) {
            int col = hb + nj * 8 + 2 * lc;
            *(__half2*)(Oh + r * LDH + col) =
                __floats2half2_rn(o[mi][nj][0] * invlo[mi],
                                  o[mi][nj][1] * invlo[mi]);
            *(__half2*)(Oh + (r + 8) * LDH + col) =
                __floats2half2_rn(o[mi][nj][2] * invhi[mi],
                                  o[mi][nj][3] * invhi[mi]);
        }
    }
    __syncthreads();   // O complete, Wp loaded

    // ---- proj GEMM: out = O * Wp^T + bias, scatter to [B,N,C] fp32 ----
    const uint32_t* Ow = (const uint32_t*)Oh;
    float c[2][4][4];
    #pragma unroll
    for (int mi = 0; mi < 2; mi++)
        #pragma unroll
        for (int nj = 0; nj < 4; nj++)
            #pragma unroll
            for (int q = 0; q < 4; q++) c[mi][nj][q] = 0.f;

    #pragma unroll
    for (int kt = 0; kt < 8; kt++) {
        uint32_t a[2][4];
        #pragma unroll
        for (int mi = 0; mi < 2; mi++) {
            int abase = (m0 + mi * 16 + lr) * LDW + kt * 8 + lc;
            a[mi][0] = Ow[abase];
            a[mi][1] = Ow[abase + 8 * LDW];
            a[mi][2] = Ow[abase + 4];
            a[mi][3] = Ow[abase + 8 * LDW + 4];
        }
        #pragma unroll
        for (int nj = 0; nj < 4; nj++) {
            uint32_t bfr[2];
            int bbase = (n0 + nj * 8 + lr) * LDW + kt * 8 + lc;
            bfr[0] = Ww[bbase];
            bfr[1] = Ww[bbase + 4];
            mma_f16(c[0][nj], a[0], bfr);
            mma_f16(c[1][nj], a[1], bfr);
        }
    }

    #pragma unroll
    for (int mi = 0; mi < 2; mi++) {
        int r = m0 + mi * 16 + lr;
        int n0t = token_index(g0 + (r >> 6), r & 63);
        int n1t = token_index(g0 + ((r + 8) >> 6), (r + 8) & 63);
        float* r0 = out + ((size_t)b * NTOK + n0t) * C_;
        float* r1 = out + ((size_t)b * NTOK + n1t) * C_;
        #pragma unroll
        for (int nj = 0; nj < 4; nj++) {
            int col = n0 + nj * 8 + 2 * lc;
            float bx = bp[col], by = bp[col + 1];
            *(float2*)(r0 + col) = make_float2(c[mi][nj][0] + bx,
                                               c[mi][nj][1] + by);
            *(float2*)(r1 + col) = make_float2(c[mi][nj][2] + bx,
                                               c[mi][nj][3] + by);
        }
    }
}

// ---------------------------------------------------------------------------
extern "C" void kernel_launch(void* const* d_in, const int* in_sizes, int n_in,
                              void* d_out, int out_size) {
    (void)in_sizes; (void)n_in; (void)out_size;
    const float* x      = (const float*)d_in[0];
    const float* w_qkv  = (const float*)d_in[1];
    const float* w_proj = (const float*)d_in[2];
    const float* b_proj = (const float*)d_in[3];
    float* out = (float*)d_out;

    cudaFuncSetAttribute(fused_all,
                         cudaFuncAttributeMaxDynamicSharedMemorySize, SMEM_FUSED);

    cvt_weights<<<64, 256>>>(w_qkv, w_proj);
    fused_all<<<1024, 512, SMEM_FUSED>>>(x, b_proj, out);
}